// round 5
// baseline (speedup 1.0000x reference)
#include <cuda_runtime.h>
#include <cuda_bf16.h>
#include <cstdint>

#define EMB    1024
#define HEADD  64
#define BATCH  4
#define SEQ    4096
#define NROWS  (BATCH * SEQ)      // 16384
#define NQT    64                 // 64-row q tiles per batch
#define NJ     160                // chunk items per batch
#define NITEM  (NJ * BATCH)       // 640
#define PART_STRIDE 4224          // 64*64 O + 64 m + 64 l

// split bf16 planes of Q, K (row-major [row][dim]) and V (transposed [b][dim][seq])
__device__ __align__(16) __nv_bfloat16 g_qh[NROWS * HEADD], g_ql[NROWS * HEADD];
__device__ __align__(16) __nv_bfloat16 g_kh[NROWS * HEADD], g_kl[NROWS * HEADD];
__device__ __align__(16) __nv_bfloat16 g_vth[NROWS * HEADD], g_vtl[NROWS * HEADD];
__device__ __align__(16) float g_part[(size_t)NITEM * PART_STRIDE];
__device__ int g_ctr;

__global__ void reset_ctr_kernel() { g_ctr = 0; }

// ---------------------------------------------------------------------------
// helpers
// ---------------------------------------------------------------------------
__device__ __forceinline__ uint32_t pack2(float a, float b) {
    __nv_bfloat162 t = __floats2bfloat162_rn(a, b);
    return *reinterpret_cast<uint32_t*>(&t);
}
__device__ __forceinline__ void splitf(float v, float& h, float& l) {
    h = __bfloat162float(__float2bfloat16(v));
    l = v - h;
}
__device__ __forceinline__ void mma16816(float* d, const uint32_t* a,
                                         uint32_t b0, uint32_t b1) {
    asm volatile(
        "mma.sync.aligned.m16n8k16.row.col.f32.bf16.bf16.f32 "
        "{%0,%1,%2,%3}, {%4,%5,%6,%7}, {%8,%9}, {%0,%1,%2,%3};\n"
        : "+f"(d[0]), "+f"(d[1]), "+f"(d[2]), "+f"(d[3])
        : "r"(a[0]), "r"(a[1]), "r"(a[2]), "r"(a[3]), "r"(b0), "r"(b1));
}

// ---------------------------------------------------------------------------
// QKV projection: [16384 x 1024] @ [1024 x 64] + b, bf16x2 split MMA.
// grid (128, 3), block 256 (8 warps, warp tile 16x64). BK=32.
// Writes Q/K as hi/lo planes [row][dim]; V as hi/lo planes transposed
// [b][dim][seq] so attention's PV B-operand is a coalesced copy.
// ---------------------------------------------------------------------------
__global__ __launch_bounds__(256) void qkv_kernel(
    const float* __restrict__ x,
    const float* __restrict__ Wq, const float* __restrict__ bq,
    const float* __restrict__ Wk, const float* __restrict__ bk,
    const float* __restrict__ Wv, const float* __restrict__ bv)
{
    const int sel = blockIdx.y;
    const float* W    = sel == 0 ? Wq : (sel == 1 ? Wk : Wv);
    const float* bias = sel == 0 ? bq : (sel == 1 ? bk : bv);

    __shared__ __align__(16) __nv_bfloat16 Xh[128 * 40], Xl[128 * 40];
    __shared__ __align__(16) __nv_bfloat16 Wth[64 * 40], Wtl[64 * 40];

    const int t = threadIdx.x, w = t >> 5, lane = t & 31;
    const int row0 = blockIdx.x * 128;

    float acc[8][4];
    #pragma unroll
    for (int n = 0; n < 8; n++)
        #pragma unroll
        for (int c = 0; c < 4; c++) acc[n][c] = 0.f;

    for (int k0 = 0; k0 < EMB; k0 += 32) {
        __syncthreads();
        // X tile 128x32 fp32 -> split hi/lo bf16 (row stride 40 bf16)
        #pragma unroll
        for (int i = 0; i < 4; i++) {
            const int idx4 = t + 256 * i;
            const int r = idx4 >> 3, c = (idx4 & 7) << 2;
            const float4 v = *(const float4*)(x + (size_t)(row0 + r) * EMB + k0 + c);
            float h0, l0, h1, l1, h2, l2, h3, l3;
            splitf(v.x, h0, l0); splitf(v.y, h1, l1);
            splitf(v.z, h2, l2); splitf(v.w, h3, l3);
            uint32_t* dh = (uint32_t*)Xh + r * 20 + (c >> 1);
            uint32_t* dl = (uint32_t*)Xl + r * 20 + (c >> 1);
            dh[0] = pack2(h0, h1); dh[1] = pack2(h2, h3);
            dl[0] = pack2(l0, l1); dl[1] = pack2(l2, l3);
        }
        // W tile 32x64 fp32 -> transposed hi/lo Wt[n][k] (row stride 40)
        #pragma unroll
        for (int i = 0; i < 8; i++) {
            const int idx = t + 256 * i;
            const int k = idx >> 6, n = idx & 63;
            const float f = W[(size_t)(k0 + k) * HEADD + n];
            float h, l; splitf(f, h, l);
            Wth[n * 40 + k] = __float2bfloat16(h);
            Wtl[n * 40 + k] = __float2bfloat16(l);
        }
        __syncthreads();

        #pragma unroll
        for (int s = 0; s < 2; s++) {
            const int ar = (w << 4) + (lane >> 2);
            const int ac = ((lane & 3) << 1) + (s << 4);
            uint32_t ah[4], al[4];
            ah[0] = *(const uint32_t*)&Xh[ar * 40 + ac];
            ah[1] = *(const uint32_t*)&Xh[(ar + 8) * 40 + ac];
            ah[2] = *(const uint32_t*)&Xh[ar * 40 + ac + 8];
            ah[3] = *(const uint32_t*)&Xh[(ar + 8) * 40 + ac + 8];
            al[0] = *(const uint32_t*)&Xl[ar * 40 + ac];
            al[1] = *(const uint32_t*)&Xl[(ar + 8) * 40 + ac];
            al[2] = *(const uint32_t*)&Xl[ar * 40 + ac + 8];
            al[3] = *(const uint32_t*)&Xl[(ar + 8) * 40 + ac + 8];
            #pragma unroll
            for (int n = 0; n < 8; n++) {
                const int br = (n << 3) + (lane >> 2);
                const uint32_t bh0 = *(const uint32_t*)&Wth[br * 40 + ac];
                const uint32_t bh1 = *(const uint32_t*)&Wth[br * 40 + ac + 8];
                const uint32_t bl0 = *(const uint32_t*)&Wtl[br * 40 + ac];
                const uint32_t bl1 = *(const uint32_t*)&Wtl[br * 40 + ac + 8];
                mma16816(acc[n], ah, bh0, bh1);
                mma16816(acc[n], ah, bl0, bl1);
                mma16816(acc[n], al, bh0, bh1);
            }
        }
    }

    // epilogue: +bias, split, store
    const int r0 = row0 + (w << 4) + (lane >> 2);
    const int r1 = r0 + 8;
    #pragma unroll
    for (int n = 0; n < 8; n++) {
        const int col0 = (n << 3) + ((lane & 3) << 1);
        const float b0 = bias[col0], b1 = bias[col0 + 1];
        const float v00 = acc[n][0] + b0, v01 = acc[n][1] + b1;
        const float v10 = acc[n][2] + b0, v11 = acc[n][3] + b1;
        float h00, l00, h01, l01, h10, l10, h11, l11;
        splitf(v00, h00, l00); splitf(v01, h01, l01);
        splitf(v10, h10, l10); splitf(v11, h11, l11);
        if (sel < 2) {
            __nv_bfloat16* oh = sel ? g_kh : g_qh;
            __nv_bfloat16* ol = sel ? g_kl : g_ql;
            ((uint32_t*)oh)[r0 * 32 + (col0 >> 1)] = pack2(h00, h01);
            ((uint32_t*)oh)[r1 * 32 + (col0 >> 1)] = pack2(h10, h11);
            ((uint32_t*)ol)[r0 * 32 + (col0 >> 1)] = pack2(l00, l01);
            ((uint32_t*)ol)[r1 * 32 + (col0 >> 1)] = pack2(l10, l11);
        } else {
            const int b0i = r0 >> 12, s0 = r0 & 4095;
            const int b1i = r1 >> 12, s1 = r1 & 4095;
            g_vth[((size_t)b0i * 64 + col0) * SEQ + s0]     = __float2bfloat16(h00);
            g_vth[((size_t)b0i * 64 + col0 + 1) * SEQ + s0] = __float2bfloat16(h01);
            g_vth[((size_t)b1i * 64 + col0) * SEQ + s1]     = __float2bfloat16(h10);
            g_vth[((size_t)b1i * 64 + col0 + 1) * SEQ + s1] = __float2bfloat16(h11);
            g_vtl[((size_t)b0i * 64 + col0) * SEQ + s0]     = __float2bfloat16(l00);
            g_vtl[((size_t)b0i * 64 + col0 + 1) * SEQ + s0] = __float2bfloat16(l01);
            g_vtl[((size_t)b1i * 64 + col0) * SEQ + s1]     = __float2bfloat16(l10);
            g_vtl[((size_t)b1i * 64 + col0 + 1) * SEQ + s1] = __float2bfloat16(l11);
        }
    }
}

// ---------------------------------------------------------------------------
// item decode: per batch, 160 (qt, chunk) items, heavy q-tiles first.
// qt 48-63: 4 chunks, 32-47: 3, 16-31: 2, 0-15: 1. Chunk = 16 k-tiles.
// ---------------------------------------------------------------------------
__device__ __forceinline__ void decode_j(int j, int& qt, int& c) {
    if (j < 64)       { qt = 63 - (j >> 2); c = j & 3; }
    else if (j < 112) { const int r = j - 64;  qt = 47 - r / 3;    c = r % 3; }
    else if (j < 144) { const int r = j - 112; qt = 31 - (r >> 1); c = r & 1; }
    else              { qt = 15 - (j - 144); c = 0; }
}
__device__ __forceinline__ int j_of(int qt, int c) {
    if (qt >= 48) return (63 - qt) * 4 + c;
    if (qt >= 32) return 64 + (47 - qt) * 3 + c;
    if (qt >= 16) return 112 + (31 - qt) * 2 + c;
    return 144 + (15 - qt);
}

// ---------------------------------------------------------------------------
// Flash attention on bf16x2 MMA. Block = 128 threads (4 warps x 16 q-rows).
// Item = (batch, 64-row q-tile, <=16 k-tile chunk); partial (O, m, l) to gmem.
// smem (dyn): Qh Ql Kh Kl Vh Vl, each 64x72 bf16 -> 55296 B.
// ---------------------------------------------------------------------------
__global__ __launch_bounds__(128, 3) void attn_kernel()
{
    extern __shared__ __align__(16) __nv_bfloat16 sm[];
    __nv_bfloat16* Qh = sm;
    __nv_bfloat16* Ql = sm + 64 * 72;
    __nv_bfloat16* Kh = sm + 2 * 64 * 72;
    __nv_bfloat16* Kl = sm + 3 * 64 * 72;
    __nv_bfloat16* Vh = sm + 4 * 64 * 72;
    __nv_bfloat16* Vl = sm + 5 * 64 * 72;
    __shared__ int s_item;

    const int t = threadIdx.x, w = t >> 5, lane = t & 31;

    for (;;) {
        if (t == 0) s_item = atomicAdd(&g_ctr, 1);
        __syncthreads();
        const int item = s_item;
        if (item >= NITEM) return;
        const int j = item >> 2, b = item & 3;
        int qt, c; decode_j(j, qt, c);
        const int kt0 = c * 16;
        const int kt1 = min(kt0 + 16, qt + 1);

        // Q tile (hi/lo) -> smem, stride 72 bf16 (2048 uint32 per plane)
        {
            const uint32_t* sh = (const uint32_t*)g_qh + (size_t)(b * SEQ + qt * 64) * 32;
            const uint32_t* sl = (const uint32_t*)g_ql + (size_t)(b * SEQ + qt * 64) * 32;
            #pragma unroll
            for (int i = 0; i < 16; i++) {
                const int idx = t + 128 * i;
                const int r = idx >> 5, cc = idx & 31;
                ((uint32_t*)Qh)[r * 36 + cc] = sh[r * 32 + cc];
                ((uint32_t*)Ql)[r * 36 + cc] = sl[r * 32 + cc];
            }
        }

        float m0 = -1e30f, m1 = -1e30f, lsum0 = 0.f, lsum1 = 0.f;
        float o[8][4];
        #pragma unroll
        for (int n = 0; n < 8; n++)
            #pragma unroll
            for (int cc = 0; cc < 4; cc++) o[n][cc] = 0.f;

        const int qg0 = qt * 64 + (w << 4) + (lane >> 2);
        const int qg1 = qg0 + 8;

        for (int kt = kt0; kt < kt1; kt++) {
            __syncthreads();
            // K/V tiles: 64 rows x 32 uint32 per plane -> 2048 uint32 each,
            // 128 threads x 16 iterations.  (Round-3 bug: this ran i<8 and
            // left rows 32-63 uninitialized -> NaN.)
            {
                const uint32_t* sh = (const uint32_t*)g_kh + (size_t)(b * SEQ + kt * 64) * 32;
                const uint32_t* sl = (const uint32_t*)g_kl + (size_t)(b * SEQ + kt * 64) * 32;
                const uint32_t* vh = (const uint32_t*)g_vth + (size_t)b * 64 * 2048 + kt * 32;
                const uint32_t* vl = (const uint32_t*)g_vtl + (size_t)b * 64 * 2048 + kt * 32;
                #pragma unroll
                for (int i = 0; i < 16; i++) {
                    const int idx = t + 128 * i;
                    const int r = idx >> 5, cc = idx & 31;
                    ((uint32_t*)Kh)[r * 36 + cc] = sh[r * 32 + cc];
                    ((uint32_t*)Kl)[r * 36 + cc] = sl[r * 32 + cc];
                    ((uint32_t*)Vh)[r * 36 + cc] = vh[(size_t)r * 2048 + cc];
                    ((uint32_t*)Vl)[r * 36 + cc] = vl[(size_t)r * 2048 + cc];
                }
            }
            __syncthreads();

            // scores S = Q K^T (warp tile 16x64)
            float s[8][4];
            #pragma unroll
            for (int n = 0; n < 8; n++)
                #pragma unroll
                for (int cc = 0; cc < 4; cc++) s[n][cc] = 0.f;
            #pragma unroll
            for (int ss = 0; ss < 4; ss++) {
                const int ar = (w << 4) + (lane >> 2);
                const int ac = ((lane & 3) << 1) + (ss << 4);
                uint32_t ah[4], al[4];
                ah[0] = *(const uint32_t*)&Qh[ar * 72 + ac];
                ah[1] = *(const uint32_t*)&Qh[(ar + 8) * 72 + ac];
                ah[2] = *(const uint32_t*)&Qh[ar * 72 + ac + 8];
                ah[3] = *(const uint32_t*)&Qh[(ar + 8) * 72 + ac + 8];
                al[0] = *(const uint32_t*)&Ql[ar * 72 + ac];
                al[1] = *(const uint32_t*)&Ql[(ar + 8) * 72 + ac];
                al[2] = *(const uint32_t*)&Ql[ar * 72 + ac + 8];
                al[3] = *(const uint32_t*)&Ql[(ar + 8) * 72 + ac + 8];
                #pragma unroll
                for (int n = 0; n < 8; n++) {
                    const int br = (n << 3) + (lane >> 2);
                    const uint32_t bh0 = *(const uint32_t*)&Kh[br * 72 + ac];
                    const uint32_t bh1 = *(const uint32_t*)&Kh[br * 72 + ac + 8];
                    const uint32_t bl0 = *(const uint32_t*)&Kl[br * 72 + ac];
                    const uint32_t bl1 = *(const uint32_t*)&Kl[br * 72 + ac + 8];
                    mma16816(s[n], ah, bh0, bh1);
                    mma16816(s[n], ah, bl0, bl1);
                    mma16816(s[n], al, bh0, bh1);
                }
            }

            // softmax (online, on fragments)
            const bool diag = (kt == qt);
            float mx0 = -1e30f, mx1 = -1e30f;
            #pragma unroll
            for (int n = 0; n < 8; n++) {
                const int kg = kt * 64 + (n << 3) + ((lane & 3) << 1);
                float v0 = s[n][0] * 0.125f, v1 = s[n][1] * 0.125f;
                float v2 = s[n][2] * 0.125f, v3 = s[n][3] * 0.125f;
                if (diag) {
                    if (kg     > qg0) v0 = -1e30f;
                    if (kg + 1 > qg0) v1 = -1e30f;
                    if (kg     > qg1) v2 = -1e30f;
                    if (kg + 1 > qg1) v3 = -1e30f;
                }
                s[n][0] = v0; s[n][1] = v1; s[n][2] = v2; s[n][3] = v3;
                mx0 = fmaxf(mx0, fmaxf(v0, v1));
                mx1 = fmaxf(mx1, fmaxf(v2, v3));
            }
            mx0 = fmaxf(mx0, __shfl_xor_sync(0xffffffffu, mx0, 1));
            mx0 = fmaxf(mx0, __shfl_xor_sync(0xffffffffu, mx0, 2));
            mx1 = fmaxf(mx1, __shfl_xor_sync(0xffffffffu, mx1, 1));
            mx1 = fmaxf(mx1, __shfl_xor_sync(0xffffffffu, mx1, 2));
            const float mn0 = fmaxf(m0, mx0), mn1 = fmaxf(m1, mx1);
            const float cr0 = __expf(m0 - mn0), cr1 = __expf(m1 - mn1);
            m0 = mn0; m1 = mn1;

            float rs0 = 0.f, rs1 = 0.f;
            uint32_t pah[4][4], pal[4][4];
            #pragma unroll
            for (int n = 0; n < 8; n++) {
                const float p0 = __expf(s[n][0] - mn0), p1 = __expf(s[n][1] - mn0);
                const float p2 = __expf(s[n][2] - mn1), p3 = __expf(s[n][3] - mn1);
                rs0 += p0 + p1; rs1 += p2 + p3;
                float h0, l0, h1, l1, h2, l2, h3, l3;
                splitf(p0, h0, l0); splitf(p1, h1, l1);
                splitf(p2, h2, l2); splitf(p3, h3, l3);
                const int ss = n >> 1, hf = (n & 1) << 1;
                pah[ss][hf]     = pack2(h0, h1);
                pah[ss][hf + 1] = pack2(h2, h3);
                pal[ss][hf]     = pack2(l0, l1);
                pal[ss][hf + 1] = pack2(l2, l3);
            }
            rs0 += __shfl_xor_sync(0xffffffffu, rs0, 1);
            rs0 += __shfl_xor_sync(0xffffffffu, rs0, 2);
            rs1 += __shfl_xor_sync(0xffffffffu, rs1, 1);
            rs1 += __shfl_xor_sync(0xffffffffu, rs1, 2);
            lsum0 = lsum0 * cr0 + rs0;
            lsum1 = lsum1 * cr1 + rs1;
            #pragma unroll
            for (int n = 0; n < 8; n++) {
                o[n][0] *= cr0; o[n][1] *= cr0;
                o[n][2] *= cr1; o[n][3] *= cr1;
            }

            // O += P V  (A-frags = repacked P, B from transposed V tile)
            #pragma unroll
            for (int ss = 0; ss < 4; ss++) {
                const int bc = ((lane & 3) << 1) + (ss << 4);
                #pragma unroll
                for (int n = 0; n < 8; n++) {
                    const int br = (n << 3) + (lane >> 2);
                    const uint32_t bh0 = *(const uint32_t*)&Vh[br * 72 + bc];
                    const uint32_t bh1 = *(const uint32_t*)&Vh[br * 72 + bc + 8];
                    const uint32_t bl0 = *(const uint32_t*)&Vl[br * 72 + bc];
                    const uint32_t bl1 = *(const uint32_t*)&Vl[br * 72 + bc + 8];
                    mma16816(o[n], pah[ss], bh0, bh1);
                    mma16816(o[n], pah[ss], bl0, bl1);
                    mma16816(o[n], pal[ss], bh0, bh1);
                }
            }
        }

        // write partial (unnormalized O, m, l)
        float* P = g_part + (size_t)item * PART_STRIDE;
        const int r0 = (w << 4) + (lane >> 2), r1 = r0 + 8;
        #pragma unroll
        for (int n = 0; n < 8; n++) {
            const int col = (n << 3) + ((lane & 3) << 1);
            *(float2*)&P[r0 * 64 + col] = make_float2(o[n][0], o[n][1]);
            *(float2*)&P[r1 * 64 + col] = make_float2(o[n][2], o[n][3]);
        }
        if ((lane & 3) == 0) {
            P[4096 + r0] = m0; P[4096 + r1] = m1;
            P[4160 + r0] = lsum0; P[4160 + r1] = lsum1;
        }
    }
}

// ---------------------------------------------------------------------------
// combine: per (b, qt), merge <=4 chunk partials, normalize, write out.
// ---------------------------------------------------------------------------
__global__ __launch_bounds__(256) void combine_kernel(float* __restrict__ out)
{
    const int bq = blockIdx.x;
    const int b = bq & 3, qt = bq >> 2;
    const int C = (qt >> 4) + 1;
    const int t = threadIdx.x;
    const int row = t >> 2, d0 = (t & 3) << 4;

    int slot[4]; float mc[4], lc[4];
    #pragma unroll
    for (int c = 0; c < 4; c++) {
        if (c < C) {
            slot[c] = (j_of(qt, c) << 2) | b;
            mc[c] = g_part[(size_t)slot[c] * PART_STRIDE + 4096 + row];
            lc[c] = g_part[(size_t)slot[c] * PART_STRIDE + 4160 + row];
        }
    }
    float ms = -1e30f;
    for (int c = 0; c < C; c++) ms = fmaxf(ms, mc[c]);
    float wt[4], denom = 0.f;
    for (int c = 0; c < C; c++) { wt[c] = __expf(mc[c] - ms); denom += wt[c] * lc[c]; }
    const float inv = 1.0f / denom;

    const size_t orow = (size_t)(b * SEQ + qt * 64 + row) * HEADD;
    #pragma unroll
    for (int d4 = 0; d4 < 16; d4 += 4) {
        float4 a = make_float4(0.f, 0.f, 0.f, 0.f);
        for (int c = 0; c < C; c++) {
            const float4 v = *(const float4*)&g_part[(size_t)slot[c] * PART_STRIDE
                                                     + row * 64 + d0 + d4];
            a.x += wt[c] * v.x; a.y += wt[c] * v.y;
            a.z += wt[c] * v.z; a.w += wt[c] * v.w;
        }
        *(float4*)&out[orow + d0 + d4] =
            make_float4(a.x * inv, a.y * inv, a.z * inv, a.w * inv);
    }
}

// ---------------------------------------------------------------------------
extern "C" void kernel_launch(void* const* d_in, const int* in_sizes, int n_in,
                              void* d_out, int out_size)
{
    const float* x  = (const float*)d_in[0];
    const float* Wq = (const float*)d_in[1];
    const float* bq = (const float*)d_in[2];
    const float* Wk = (const float*)d_in[3];
    const float* bk = (const float*)d_in[4];
    const float* Wv = (const float*)d_in[5];
    const float* bv = (const float*)d_in[6];
    float* out = (float*)d_out;

    reset_ctr_kernel<<<1, 1>>>();
    qkv_kernel<<<dim3(128, 3), 256>>>(x, Wq, bq, Wk, bk, Wv, bv);

    const int smem = 6 * 64 * 72 * (int)sizeof(__nv_bfloat16);   // 55296 B
    cudaFuncSetAttribute(attn_kernel,
                         cudaFuncAttributeMaxDynamicSharedMemorySize, smem);
    attn_kernel<<<592, 128, smem>>>();

    combine_kernel<<<256, 256>>>(out);
}

// round 9
// speedup vs baseline: 1.0195x; 1.0195x over previous
#include <cuda_runtime.h>
#include <cuda_bf16.h>
#include <cstdint>

#define EMB    1024
#define HEADD  64
#define BATCH  4
#define SEQ    4096
#define NROWS  (BATCH * SEQ)
#define NITEM  576                 // 144 (qt,chunk) items x 4 batches
#define PART_STRIDE 8320           // 128*64 O + 128 l
#define MSHIFT 8.0f

__device__ __align__(16) __nv_bfloat16 g_qh[NROWS * HEADD], g_ql[NROWS * HEADD];
__device__ __align__(16) __nv_bfloat16 g_kh[NROWS * HEADD], g_kl[NROWS * HEADD];
__device__ __align__(16) __nv_bfloat16 g_vth[NROWS * HEADD], g_vtl[NROWS * HEADD];
__device__ __align__(16) float g_part[(size_t)NITEM * PART_STRIDE];
__device__ int g_ctr;

__global__ void reset_ctr_kernel() { g_ctr = 0; }

__device__ __forceinline__ uint32_t pack2(float a, float b) {
    __nv_bfloat162 t = __floats2bfloat162_rn(a, b);
    return *reinterpret_cast<uint32_t*>(&t);
}
__device__ __forceinline__ void splitf(float v, float& h, float& l) {
    h = __bfloat162float(__float2bfloat16(v));
    l = v - h;
}
__device__ __forceinline__ void mma16816(float* d, const uint32_t* a,
                                         uint32_t b0, uint32_t b1) {
    asm volatile(
        "mma.sync.aligned.m16n8k16.row.col.f32.bf16.bf16.f32 "
        "{%0,%1,%2,%3}, {%4,%5,%6,%7}, {%8,%9}, {%0,%1,%2,%3};\n"
        : "+f"(d[0]), "+f"(d[1]), "+f"(d[2]), "+f"(d[3])
        : "r"(a[0]), "r"(a[1]), "r"(a[2]), "r"(a[3]), "r"(b0), "r"(b1));
}

// ---------------------------------------------------------------------------
// QKV projection — ROUND-4 PROVEN VERSION (unfused, static smem 30720 B).
// grid (128, 3), block 256 (8 warps, warp tile 16x64), K-chunk 32.
// ---------------------------------------------------------------------------
__global__ __launch_bounds__(256) void qkv_kernel(
    const float* __restrict__ x,
    const float* __restrict__ Wq, const float* __restrict__ bq,
    const float* __restrict__ Wk, const float* __restrict__ bk,
    const float* __restrict__ Wv, const float* __restrict__ bv)
{
    const int sel = blockIdx.y;
    const float* W    = sel == 0 ? Wq : (sel == 1 ? Wk : Wv);
    const float* bias = sel == 0 ? bq : (sel == 1 ? bk : bv);

    __shared__ __align__(16) __nv_bfloat16 Xh[128 * 40], Xl[128 * 40];
    __shared__ __align__(16) __nv_bfloat16 Wth[64 * 40], Wtl[64 * 40];

    const int t = threadIdx.x, w = t >> 5, lane = t & 31;
    const int row0 = blockIdx.x * 128;

    float acc[8][4];
    #pragma unroll
    for (int n = 0; n < 8; n++)
        #pragma unroll
        for (int c = 0; c < 4; c++) acc[n][c] = 0.f;

    for (int k0 = 0; k0 < EMB; k0 += 32) {
        __syncthreads();
        #pragma unroll
        for (int i = 0; i < 4; i++) {
            const int idx4 = t + 256 * i;
            const int r = idx4 >> 3, c = (idx4 & 7) << 2;
            const float4 v = *(const float4*)(x + (size_t)(row0 + r) * EMB + k0 + c);
            float h0, l0, h1, l1, h2, l2, h3, l3;
            splitf(v.x, h0, l0); splitf(v.y, h1, l1);
            splitf(v.z, h2, l2); splitf(v.w, h3, l3);
            uint32_t* dh = (uint32_t*)Xh + r * 20 + (c >> 1);
            uint32_t* dl = (uint32_t*)Xl + r * 20 + (c >> 1);
            dh[0] = pack2(h0, h1); dh[1] = pack2(h2, h3);
            dl[0] = pack2(l0, l1); dl[1] = pack2(l2, l3);
        }
        #pragma unroll
        for (int i = 0; i < 8; i++) {
            const int idx = t + 256 * i;
            const int k = idx >> 6, n = idx & 63;
            const float f = W[(size_t)(k0 + k) * HEADD + n];
            float h, l; splitf(f, h, l);
            Wth[n * 40 + k] = __float2bfloat16(h);
            Wtl[n * 40 + k] = __float2bfloat16(l);
        }
        __syncthreads();

        #pragma unroll
        for (int ss = 0; ss < 2; ss++) {
            const int ar = (w << 4) + (lane >> 2);
            const int ac = ((lane & 3) << 1) + (ss << 4);
            uint32_t ah[4], al[4];
            ah[0] = *(const uint32_t*)&Xh[ar * 40 + ac];
            ah[1] = *(const uint32_t*)&Xh[(ar + 8) * 40 + ac];
            ah[2] = *(const uint32_t*)&Xh[ar * 40 + ac + 8];
            ah[3] = *(const uint32_t*)&Xh[(ar + 8) * 40 + ac + 8];
            al[0] = *(const uint32_t*)&Xl[ar * 40 + ac];
            al[1] = *(const uint32_t*)&Xl[(ar + 8) * 40 + ac];
            al[2] = *(const uint32_t*)&Xl[ar * 40 + ac + 8];
            al[3] = *(const uint32_t*)&Xl[(ar + 8) * 40 + ac + 8];
            #pragma unroll
            for (int n = 0; n < 8; n++) {
                const int br = (n << 3) + (lane >> 2);
                const uint32_t bh0 = *(const uint32_t*)&Wth[br * 40 + ac];
                const uint32_t bh1 = *(const uint32_t*)&Wth[br * 40 + ac + 8];
                const uint32_t bl0 = *(const uint32_t*)&Wtl[br * 40 + ac];
                const uint32_t bl1 = *(const uint32_t*)&Wtl[br * 40 + ac + 8];
                mma16816(acc[n], ah, bh0, bh1);
                mma16816(acc[n], ah, bl0, bl1);
                mma16816(acc[n], al, bh0, bh1);
            }
        }
    }

    const int r0 = row0 + (w << 4) + (lane >> 2);
    const int r1 = r0 + 8;
    #pragma unroll
    for (int n = 0; n < 8; n++) {
        const int col0 = (n << 3) + ((lane & 3) << 1);
        const float b0 = bias[col0], b1 = bias[col0 + 1];
        const float v00 = acc[n][0] + b0, v01 = acc[n][1] + b1;
        const float v10 = acc[n][2] + b0, v11 = acc[n][3] + b1;
        float h00, l00, h01, l01, h10, l10, h11, l11;
        splitf(v00, h00, l00); splitf(v01, h01, l01);
        splitf(v10, h10, l10); splitf(v11, h11, l11);
        if (sel < 2) {
            __nv_bfloat16* oh = sel ? g_kh : g_qh;
            __nv_bfloat16* ol = sel ? g_kl : g_ql;
            ((uint32_t*)oh)[r0 * 32 + (col0 >> 1)] = pack2(h00, h01);
            ((uint32_t*)oh)[r1 * 32 + (col0 >> 1)] = pack2(h10, h11);
            ((uint32_t*)ol)[r0 * 32 + (col0 >> 1)] = pack2(l00, l01);
            ((uint32_t*)ol)[r1 * 32 + (col0 >> 1)] = pack2(l10, l11);
        } else {
            const int b0i = r0 >> 12, s0 = r0 & 4095;
            const int b1i = r1 >> 12, s1 = r1 & 4095;
            g_vth[((size_t)b0i * 64 + col0) * SEQ + s0]     = __float2bfloat16(h00);
            g_vth[((size_t)b0i * 64 + col0 + 1) * SEQ + s0] = __float2bfloat16(h01);
            g_vth[((size_t)b1i * 64 + col0) * SEQ + s1]     = __float2bfloat16(h10);
            g_vth[((size_t)b1i * 64 + col0 + 1) * SEQ + s1] = __float2bfloat16(h11);
            g_vtl[((size_t)b0i * 64 + col0) * SEQ + s0]     = __float2bfloat16(l00);
            g_vtl[((size_t)b0i * 64 + col0 + 1) * SEQ + s0] = __float2bfloat16(l01);
            g_vtl[((size_t)b1i * 64 + col0) * SEQ + s1]     = __float2bfloat16(l10);
            g_vtl[((size_t)b1i * 64 + col0 + 1) * SEQ + s1] = __float2bfloat16(l11);
        }
    }
}

// ---------------------------------------------------------------------------
// Work items: per batch, q-tile qt (128 rows, qt 0..31) has (qt+4)>>2 chunks
// of <=8 64-key k-tiles. 144 items/batch, heavy (high qt) first.
// ---------------------------------------------------------------------------
__device__ __forceinline__ void decode_item(int j, int& qt, int& c) {
    int acc = 0;
    for (int q = 31; q >= 0; q--) {
        const int n = (q + 4) >> 2;
        if (j < acc + n) { qt = q; c = j - acc; return; }
        acc += n;
    }
    qt = 0; c = 0;
}
__device__ __forceinline__ int base_of(int qt) {
    int acc = 0;
    for (int q = 31; q > qt; q--) acc += (q + 4) >> 2;
    return acc;
}

// ---------------------------------------------------------------------------
// Flash attention, FIXED-SHIFT softmax (m = MSHIFT, no online rescale).
// Block 256 thr (8 warps x 16 q-rows = 128-row q-tile). Partial (O,l) -> gmem.
// smem: Qh/Ql 128x72, Kh/Kl/Vh/Vl 64x72 bf16 = 73728 B (dynamic).
// ---------------------------------------------------------------------------
__global__ __launch_bounds__(256, 2) void attn_kernel()
{
    extern __shared__ __align__(16) __nv_bfloat16 sm[];
    __nv_bfloat16* Qh = sm;
    __nv_bfloat16* Ql = sm + 128 * 72;
    __nv_bfloat16* Kh = sm + 2 * 128 * 72;
    __nv_bfloat16* Kl = Kh + 64 * 72;
    __nv_bfloat16* Vh = Kl + 64 * 72;
    __nv_bfloat16* Vl = Vh + 64 * 72;
    __shared__ int s_item;

    const int t = threadIdx.x, w = t >> 5, lane = t & 31;

    for (;;) {
        if (t == 0) s_item = atomicAdd(&g_ctr, 1);
        __syncthreads();
        const int item = s_item;
        if (item >= NITEM) return;
        const int j = item >> 2, b = item & 3;
        int qt, c; decode_item(j, qt, c);
        const int kt0 = c * 8;
        const int kt1 = min(kt0 + 8, 2 * qt + 2);

        // Q tile 128 rows (hi/lo), 4096 words per plane
        {
            const uint32_t* sh = (const uint32_t*)g_qh + (size_t)(b * SEQ + qt * 128) * 32;
            const uint32_t* sl = (const uint32_t*)g_ql + (size_t)(b * SEQ + qt * 128) * 32;
            #pragma unroll
            for (int i = 0; i < 16; i++) {
                const int idx = t + 256 * i;
                const int r = idx >> 5, cc = idx & 31;
                ((uint32_t*)Qh)[r * 36 + cc] = sh[r * 32 + cc];
                ((uint32_t*)Ql)[r * 36 + cc] = sl[r * 32 + cc];
            }
        }

        float l0 = 0.f, l1 = 0.f;
        float o[8][4];
        #pragma unroll
        for (int n = 0; n < 8; n++)
            #pragma unroll
            for (int cc = 0; cc < 4; cc++) o[n][cc] = 0.f;

        const int qg0 = qt * 128 + (w << 4) + (lane >> 2);
        const int qg1 = qg0 + 8;

        for (int kt = kt0; kt < kt1; kt++) {
            __syncthreads();
            // K/V 64-row tiles: 2048 words per plane, 256 thr x 8 iters
            {
                const uint32_t* sh = (const uint32_t*)g_kh + (size_t)(b * SEQ + kt * 64) * 32;
                const uint32_t* sl = (const uint32_t*)g_kl + (size_t)(b * SEQ + kt * 64) * 32;
                const uint32_t* vh = (const uint32_t*)g_vth + (size_t)b * 64 * 2048 + kt * 32;
                const uint32_t* vl = (const uint32_t*)g_vtl + (size_t)b * 64 * 2048 + kt * 32;
                #pragma unroll
                for (int i = 0; i < 8; i++) {
                    const int idx = t + 256 * i;
                    const int r = idx >> 5, cc = idx & 31;
                    ((uint32_t*)Kh)[r * 36 + cc] = sh[r * 32 + cc];
                    ((uint32_t*)Kl)[r * 36 + cc] = sl[r * 32 + cc];
                    ((uint32_t*)Vh)[r * 36 + cc] = vh[(size_t)r * 2048 + cc];
                    ((uint32_t*)Vl)[r * 36 + cc] = vl[(size_t)r * 2048 + cc];
                }
            }
            __syncthreads();

            // S = Q K^T
            float s[8][4];
            #pragma unroll
            for (int n = 0; n < 8; n++)
                #pragma unroll
                for (int cc = 0; cc < 4; cc++) s[n][cc] = 0.f;
            #pragma unroll
            for (int ss = 0; ss < 4; ss++) {
                const int ar = (w << 4) + (lane >> 2);
                const int ac = ((lane & 3) << 1) + (ss << 4);
                uint32_t ah[4], al[4];
                ah[0] = *(const uint32_t*)&Qh[ar * 72 + ac];
                ah[1] = *(const uint32_t*)&Qh[(ar + 8) * 72 + ac];
                ah[2] = *(const uint32_t*)&Qh[ar * 72 + ac + 8];
                ah[3] = *(const uint32_t*)&Qh[(ar + 8) * 72 + ac + 8];
                al[0] = *(const uint32_t*)&Ql[ar * 72 + ac];
                al[1] = *(const uint32_t*)&Ql[(ar + 8) * 72 + ac];
                al[2] = *(const uint32_t*)&Ql[ar * 72 + ac + 8];
                al[3] = *(const uint32_t*)&Ql[(ar + 8) * 72 + ac + 8];
                #pragma unroll
                for (int n = 0; n < 8; n++) {
                    const int br = (n << 3) + (lane >> 2);
                    const uint32_t bh0 = *(const uint32_t*)&Kh[br * 72 + ac];
                    const uint32_t bh1 = *(const uint32_t*)&Kh[br * 72 + ac + 8];
                    const uint32_t bl0 = *(const uint32_t*)&Kl[br * 72 + ac];
                    const uint32_t bl1 = *(const uint32_t*)&Kl[br * 72 + ac + 8];
                    mma16816(s[n], ah, bh0, bh1);
                    mma16816(s[n], ah, bl0, bl1);
                    mma16816(s[n], al, bh0, bh1);
                }
            }

            // fixed-shift softmax: p = exp(s/8 - MSHIFT); masked -> exact 0
            const bool diag = (kt >= 2 * qt);
            uint32_t pah[4][4], pal[4][4];
            #pragma unroll
            for (int n = 0; n < 8; n++) {
                const int kg = kt * 64 + (n << 3) + ((lane & 3) << 1);
                float v0 = fmaf(s[n][0], 0.125f, -MSHIFT);
                float v1 = fmaf(s[n][1], 0.125f, -MSHIFT);
                float v2 = fmaf(s[n][2], 0.125f, -MSHIFT);
                float v3 = fmaf(s[n][3], 0.125f, -MSHIFT);
                if (diag) {
                    if (kg     > qg0) v0 = -1e30f;
                    if (kg + 1 > qg0) v1 = -1e30f;
                    if (kg     > qg1) v2 = -1e30f;
                    if (kg + 1 > qg1) v3 = -1e30f;
                }
                const float p0 = __expf(v0), p1 = __expf(v1);
                const float p2 = __expf(v2), p3 = __expf(v3);
                l0 += p0 + p1; l1 += p2 + p3;
                float h0, lo0, h1, lo1, h2, lo2, h3, lo3;
                splitf(p0, h0, lo0); splitf(p1, h1, lo1);
                splitf(p2, h2, lo2); splitf(p3, h3, lo3);
                const int ss = n >> 1, hf = (n & 1) << 1;
                pah[ss][hf]     = pack2(h0, h1);
                pah[ss][hf + 1] = pack2(h2, h3);
                pal[ss][hf]     = pack2(lo0, lo1);
                pal[ss][hf + 1] = pack2(lo2, lo3);
            }

            // O += P V
            #pragma unroll
            for (int ss = 0; ss < 4; ss++) {
                const int bc = ((lane & 3) << 1) + (ss << 4);
                #pragma unroll
                for (int n = 0; n < 8; n++) {
                    const int br = (n << 3) + (lane >> 2);
                    const uint32_t bh0 = *(const uint32_t*)&Vh[br * 72 + bc];
                    const uint32_t bh1 = *(const uint32_t*)&Vh[br * 72 + bc + 8];
                    const uint32_t bl0 = *(const uint32_t*)&Vl[br * 72 + bc];
                    const uint32_t bl1 = *(const uint32_t*)&Vl[br * 72 + bc + 8];
                    mma16816(o[n], pah[ss], bh0, bh1);
                    mma16816(o[n], pah[ss], bl0, bl1);
                    mma16816(o[n], pal[ss], bh0, bh1);
                }
            }
        }

        // row-sum reduce l across the 4 lanes of each row, then store partials
        l0 += __shfl_xor_sync(0xffffffffu, l0, 1);
        l0 += __shfl_xor_sync(0xffffffffu, l0, 2);
        l1 += __shfl_xor_sync(0xffffffffu, l1, 1);
        l1 += __shfl_xor_sync(0xffffffffu, l1, 2);

        float* P = g_part + (size_t)item * PART_STRIDE;
        const int r0 = (w << 4) + (lane >> 2), r1 = r0 + 8;
        #pragma unroll
        for (int n = 0; n < 8; n++) {
            const int col = (n << 3) + ((lane & 3) << 1);
            *(float2*)&P[r0 * 64 + col] = make_float2(o[n][0], o[n][1]);
            *(float2*)&P[r1 * 64 + col] = make_float2(o[n][2], o[n][3]);
        }
        if ((lane & 3) == 0) {
            P[8192 + r0] = l0;
            P[8192 + r1] = l1;
        }
        __syncthreads();
    }
}

// ---------------------------------------------------------------------------
// combine: fixed shift -> plain sums. grid 128 (b,qt), 256 thr.
// ---------------------------------------------------------------------------
__global__ __launch_bounds__(256) void combine_kernel(float* __restrict__ out)
{
    const int blk = blockIdx.x;
    const int b = blk & 3, qt = blk >> 2;
    const int C = (qt + 4) >> 2;
    const int base = base_of(qt);
    const int t = threadIdx.x;
    const int row = t >> 1, d0 = (t & 1) << 5;

    float lsum = 0.f;
    for (int c = 0; c < C; c++)
        lsum += g_part[(size_t)((base + c) << 2 | b) * PART_STRIDE + 8192 + row];
    const float inv = 1.0f / lsum;

    const size_t orow = (size_t)(b * SEQ + qt * 128 + row) * HEADD;
    #pragma unroll
    for (int d4 = 0; d4 < 32; d4 += 4) {
        float4 a = make_float4(0.f, 0.f, 0.f, 0.f);
        for (int c = 0; c < C; c++) {
            const float4 v = *(const float4*)&g_part[
                (size_t)((base + c) << 2 | b) * PART_STRIDE + row * 64 + d0 + d4];
            a.x += v.x; a.y += v.y; a.z += v.z; a.w += v.w;
        }
        *(float4*)&out[orow + d0 + d4] =
            make_float4(a.x * inv, a.y * inv, a.z * inv, a.w * inv);
    }
}

// ---------------------------------------------------------------------------
extern "C" void kernel_launch(void* const* d_in, const int* in_sizes, int n_in,
                              void* d_out, int out_size)
{
    const float* x  = (const float*)d_in[0];
    const float* Wq = (const float*)d_in[1];
    const float* bq = (const float*)d_in[2];
    const float* Wk = (const float*)d_in[3];
    const float* bk = (const float*)d_in[4];
    const float* Wv = (const float*)d_in[5];
    const float* bv = (const float*)d_in[6];
    float* out = (float*)d_out;

    reset_ctr_kernel<<<1, 1>>>();

    qkv_kernel<<<dim3(128, 3), 256>>>(x, Wq, bq, Wk, bk, Wv, bv);

    const int smem = (2 * 128 + 4 * 64) * 72 * (int)sizeof(__nv_bfloat16); // 73728
    cudaFuncSetAttribute(attn_kernel,
                         cudaFuncAttributeMaxDynamicSharedMemorySize, smem);
    attn_kernel<<<296, 256, smem>>>();

    combine_kernel<<<128, 256>>>(out);
}

// round 11
// speedup vs baseline: 1.0380x; 1.0182x over previous
#include <cuda_runtime.h>
#include <cuda_bf16.h>
#include <cstdint>

#define EMB    1024
#define HEADD  64
#define BATCH  4
#define SEQ    4096
#define NROWS  (BATCH * SEQ)
#define NITEM  576
#define PART_STRIDE 8320           // 128*64 O + 128 l
#define MSHIFT 8.0f

__device__ __align__(16) __nv_bfloat16 g_qh[NROWS * HEADD], g_ql[NROWS * HEADD];
__device__ __align__(16) __nv_bfloat16 g_kh[NROWS * HEADD], g_kl[NROWS * HEADD];
__device__ __align__(16) __nv_bfloat16 g_vth[NROWS * HEADD], g_vtl[NROWS * HEADD];
__device__ __align__(16) float g_part[(size_t)NITEM * PART_STRIDE];
__device__ int g_ctr;

__device__ __forceinline__ uint32_t pack2(float a, float b) {
    __nv_bfloat162 t = __floats2bfloat162_rn(a, b);
    return *reinterpret_cast<uint32_t*>(&t);
}
__device__ __forceinline__ void splitf(float v, float& h, float& l) {
    h = __bfloat162float(__float2bfloat16(v));
    l = v - h;
}
__device__ __forceinline__ void mma16816(float* d, const uint32_t* a,
                                         uint32_t b0, uint32_t b1) {
    asm volatile(
        "mma.sync.aligned.m16n8k16.row.col.f32.bf16.bf16.f32 "
        "{%0,%1,%2,%3}, {%4,%5,%6,%7}, {%8,%9}, {%0,%1,%2,%3};\n"
        : "+f"(d[0]), "+f"(d[1]), "+f"(d[2]), "+f"(d[3])
        : "r"(a[0]), "r"(a[1]), "r"(a[2]), "r"(a[3]), "r"(b0), "r"(b1));
}
__device__ __forceinline__ uint32_t smem_u32(const void* p) {
    uint32_t a;
    asm("{ .reg .u64 t; cvta.to.shared.u64 t, %1; cvt.u32.u64 %0, t; }" : "=r"(a) : "l"(p));
    return a;
}
#define LDSM4(r, a)                                                          \
    asm volatile("ldmatrix.sync.aligned.m8n8.x4.shared.b16 {%0,%1,%2,%3}, [%4];" \
        : "=r"((r)[0]), "=r"((r)[1]), "=r"((r)[2]), "=r"((r)[3]) : "r"(a))

// ---------------------------------------------------------------------------
// QKV projection (round-9 proven version; also resets g_ctr).
// ---------------------------------------------------------------------------
__global__ __launch_bounds__(256) void qkv_kernel(
    const float* __restrict__ x,
    const float* __restrict__ Wq, const float* __restrict__ bq,
    const float* __restrict__ Wk, const float* __restrict__ bk,
    const float* __restrict__ Wv, const float* __restrict__ bv)
{
    if (blockIdx.x == 0 && blockIdx.y == 0 && threadIdx.x == 0) g_ctr = 0;

    const int sel = blockIdx.y;
    const float* W    = sel == 0 ? Wq : (sel == 1 ? Wk : Wv);
    const float* bias = sel == 0 ? bq : (sel == 1 ? bk : bv);

    __shared__ __align__(16) __nv_bfloat16 Xh[128 * 40], Xl[128 * 40];
    __shared__ __align__(16) __nv_bfloat16 Wth[64 * 40], Wtl[64 * 40];

    const int t = threadIdx.x, w = t >> 5, lane = t & 31;
    const int row0 = blockIdx.x * 128;

    float acc[8][4];
    #pragma unroll
    for (int n = 0; n < 8; n++)
        #pragma unroll
        for (int c = 0; c < 4; c++) acc[n][c] = 0.f;

    for (int k0 = 0; k0 < EMB; k0 += 32) {
        __syncthreads();
        #pragma unroll
        for (int i = 0; i < 4; i++) {
            const int idx4 = t + 256 * i;
            const int r = idx4 >> 3, c = (idx4 & 7) << 2;
            const float4 v = *(const float4*)(x + (size_t)(row0 + r) * EMB + k0 + c);
            float h0, l0, h1, l1, h2, l2, h3, l3;
            splitf(v.x, h0, l0); splitf(v.y, h1, l1);
            splitf(v.z, h2, l2); splitf(v.w, h3, l3);
            uint32_t* dh = (uint32_t*)Xh + r * 20 + (c >> 1);
            uint32_t* dl = (uint32_t*)Xl + r * 20 + (c >> 1);
            dh[0] = pack2(h0, h1); dh[1] = pack2(h2, h3);
            dl[0] = pack2(l0, l1); dl[1] = pack2(l2, l3);
        }
        #pragma unroll
        for (int i = 0; i < 8; i++) {
            const int idx = t + 256 * i;
            const int k = idx >> 6, n = idx & 63;
            const float f = W[(size_t)(k0 + k) * HEADD + n];
            float h, l; splitf(f, h, l);
            Wth[n * 40 + k] = __float2bfloat16(h);
            Wtl[n * 40 + k] = __float2bfloat16(l);
        }
        __syncthreads();

        #pragma unroll
        for (int ss = 0; ss < 2; ss++) {
            const int ar = (w << 4) + (lane >> 2);
            const int ac = ((lane & 3) << 1) + (ss << 4);
            uint32_t ah[4], al[4];
            ah[0] = *(const uint32_t*)&Xh[ar * 40 + ac];
            ah[1] = *(const uint32_t*)&Xh[(ar + 8) * 40 + ac];
            ah[2] = *(const uint32_t*)&Xh[ar * 40 + ac + 8];
            ah[3] = *(const uint32_t*)&Xh[(ar + 8) * 40 + ac + 8];
            al[0] = *(const uint32_t*)&Xl[ar * 40 + ac];
            al[1] = *(const uint32_t*)&Xl[(ar + 8) * 40 + ac];
            al[2] = *(const uint32_t*)&Xl[ar * 40 + ac + 8];
            al[3] = *(const uint32_t*)&Xl[(ar + 8) * 40 + ac + 8];
            #pragma unroll
            for (int n = 0; n < 8; n++) {
                const int br = (n << 3) + (lane >> 2);
                const uint32_t bh0 = *(const uint32_t*)&Wth[br * 40 + ac];
                const uint32_t bh1 = *(const uint32_t*)&Wth[br * 40 + ac + 8];
                const uint32_t bl0 = *(const uint32_t*)&Wtl[br * 40 + ac];
                const uint32_t bl1 = *(const uint32_t*)&Wtl[br * 40 + ac + 8];
                mma16816(acc[n], ah, bh0, bh1);
                mma16816(acc[n], ah, bl0, bl1);
                mma16816(acc[n], al, bh0, bh1);
            }
        }
    }

    const int r0 = row0 + (w << 4) + (lane >> 2);
    const int r1 = r0 + 8;
    #pragma unroll
    for (int n = 0; n < 8; n++) {
        const int col0 = (n << 3) + ((lane & 3) << 1);
        const float b0 = bias[col0], b1 = bias[col0 + 1];
        const float v00 = acc[n][0] + b0, v01 = acc[n][1] + b1;
        const float v10 = acc[n][2] + b0, v11 = acc[n][3] + b1;
        float h00, l00, h01, l01, h10, l10, h11, l11;
        splitf(v00, h00, l00); splitf(v01, h01, l01);
        splitf(v10, h10, l10); splitf(v11, h11, l11);
        if (sel < 2) {
            __nv_bfloat16* oh = sel ? g_kh : g_qh;
            __nv_bfloat16* ol = sel ? g_kl : g_ql;
            ((uint32_t*)oh)[r0 * 32 + (col0 >> 1)] = pack2(h00, h01);
            ((uint32_t*)oh)[r1 * 32 + (col0 >> 1)] = pack2(h10, h11);
            ((uint32_t*)ol)[r0 * 32 + (col0 >> 1)] = pack2(l00, l01);
            ((uint32_t*)ol)[r1 * 32 + (col0 >> 1)] = pack2(l10, l11);
        } else {
            const int b0i = r0 >> 12, s0 = r0 & 4095;
            const int b1i = r1 >> 12, s1 = r1 & 4095;
            g_vth[((size_t)b0i * 64 + col0) * SEQ + s0]     = __float2bfloat16(h00);
            g_vth[((size_t)b0i * 64 + col0 + 1) * SEQ + s0] = __float2bfloat16(h01);
            g_vth[((size_t)b1i * 64 + col0) * SEQ + s1]     = __float2bfloat16(h10);
            g_vth[((size_t)b1i * 64 + col0 + 1) * SEQ + s1] = __float2bfloat16(h11);
            g_vtl[((size_t)b0i * 64 + col0) * SEQ + s0]     = __float2bfloat16(l00);
            g_vtl[((size_t)b0i * 64 + col0 + 1) * SEQ + s0] = __float2bfloat16(l01);
            g_vtl[((size_t)b1i * 64 + col0) * SEQ + s1]     = __float2bfloat16(l10);
            g_vtl[((size_t)b1i * 64 + col0 + 1) * SEQ + s1] = __float2bfloat16(l11);
        }
    }
}

// ---------------------------------------------------------------------------
__device__ __forceinline__ void decode_item(int j, int& qt, int& c) {
    int acc = 0;
    for (int q = 31; q >= 0; q--) {
        const int n = (q + 4) >> 2;
        if (j < acc + n) { qt = q; c = j - acc; return; }
        acc += n;
    }
    qt = 0; c = 0;
}
__device__ __forceinline__ int base_of(int qt) {
    int acc = 0;
    for (int q = 31; q > qt; q--) acc += (q + 4) >> 2;
    return acc;
}

// ---------------------------------------------------------------------------
// Flash attention: ldmatrix frag loads, uint4 staging, softmax/PV interleave.
// smem (bytes, rows padded to 144 B): Qh 0, Ql 18432, Kh 36864, Kl 46080,
// Vh 55296, Vl 64512. Total 73728.
// ---------------------------------------------------------------------------
#define A_QH 0
#define A_QL 18432
#define A_KH 36864
#define A_KL 46080
#define A_VH 55296
#define A_VL 64512
#define ATTN_SMEM 73728

__global__ __launch_bounds__(256, 2) void attn_kernel()
{
    extern __shared__ __align__(16) char smb[];
    __shared__ int s_item;

    const int t = threadIdx.x, w = t >> 5, lane = t & 31;
    const uint32_t sb = smem_u32(smb);

    // ldmatrix lane geometry: tr = row-in-tile, tq = tile index (x4)
    const int tr = lane & 7, tq = lane >> 3;
    // A (Q): tiles (r / r+8) x (k0 / k8)
    const uint32_t uQh = sb + A_QH
        + (uint32_t)((w * 16 + tr + ((tq & 1) << 3)) * 144 + ((tq >> 1) << 4));
    const uint32_t uQl = uQh + (A_QL - A_QH);
    // B (K/V): tiles (n-oct even/odd) x (k0 / k8); np adds 2304 B (16 rows)
    const uint32_t ubase = (uint32_t)(((((tq >> 1) << 3) + tr) * 144) + ((tq & 1) << 4));
    const uint32_t uKh = sb + A_KH + ubase;
    const uint32_t uKl = sb + A_KL + ubase;
    const uint32_t uVh = sb + A_VH + ubase;
    const uint32_t uVl = sb + A_VL + ubase;

    for (;;) {
        if (t == 0) s_item = atomicAdd(&g_ctr, 1);
        __syncthreads();
        const int item = s_item;
        if (item >= NITEM) return;
        const int j = item >> 2, b = item & 3;
        int qt, c; decode_item(j, qt, c);
        const int kt0 = c * 8;
        const int kt1 = min(kt0 + 8, 2 * qt + 2);
        const int qg0 = qt * 128 + (w << 4) + (lane >> 2);
        const int qg1 = qg0 + 8;

        // stage Q: 1024 uint4 per plane (128 rows x 8 chunks)
        {
            const uint4* gqh = (const uint4*)g_qh + (size_t)(b * SEQ + qt * 128) * 8;
            const uint4* gql = (const uint4*)g_ql + (size_t)(b * SEQ + qt * 128) * 8;
            #pragma unroll
            for (int i = 0; i < 4; i++) {
                const int idx = t + 256 * i;
                const int r = idx >> 3, c16 = idx & 7;
                const uint32_t off = (uint32_t)(r * 144 + c16 * 16);
                *(uint4*)(smb + A_QH + off) = gqh[idx];
                *(uint4*)(smb + A_QL + off) = gql[idx];
            }
        }

        float l0 = 0.f, l1 = 0.f;
        float o[8][4];
        #pragma unroll
        for (int n = 0; n < 8; n++)
            #pragma unroll
            for (int cc = 0; cc < 4; cc++) o[n][cc] = 0.f;

        for (int kt = kt0; kt < kt1; kt++) {
            __syncthreads();   // prior tile's reads done before overwrite
            // stage K/V: 512 uint4 per plane (64 rows x 8 chunks)
            {
                const uint4* gkh = (const uint4*)g_kh + (size_t)(b * SEQ + kt * 64) * 8;
                const uint4* gkl = (const uint4*)g_kl + (size_t)(b * SEQ + kt * 64) * 8;
                const uint4* gvh = (const uint4*)g_vth;
                const uint4* gvl = (const uint4*)g_vtl;
                #pragma unroll
                for (int i = 0; i < 2; i++) {
                    const int idx = t + 256 * i;
                    const int r = idx >> 3, c16 = idx & 7;
                    const uint32_t off = (uint32_t)(r * 144 + c16 * 16);
                    *(uint4*)(smb + A_KH + off) = gkh[idx];
                    *(uint4*)(smb + A_KL + off) = gkl[idx];
                    const size_t vi = (size_t)(b * 64 + r) * 512 + kt * 8 + c16;
                    *(uint4*)(smb + A_VH + off) = gvh[vi];
                    *(uint4*)(smb + A_VL + off) = gvl[vi];
                }
            }
            __syncthreads();

            // S = Q K^T  (ldmatrix frags, 96 MMAs/warp)
            float s[8][4];
            #pragma unroll
            for (int n = 0; n < 8; n++)
                #pragma unroll
                for (int cc = 0; cc < 4; cc++) s[n][cc] = 0.f;
            #pragma unroll
            for (int ss = 0; ss < 4; ss++) {
                uint32_t ah[4], al[4];
                LDSM4(ah, uQh + ss * 32);
                LDSM4(al, uQl + ss * 32);
                #pragma unroll
                for (int np = 0; np < 4; np++) {
                    uint32_t kh[4], kl[4];
                    LDSM4(kh, uKh + np * 2304 + ss * 32);
                    LDSM4(kl, uKl + np * 2304 + ss * 32);
                    mma16816(s[2 * np],     ah, kh[0], kh[1]);
                    mma16816(s[2 * np],     ah, kl[0], kl[1]);
                    mma16816(s[2 * np],     al, kh[0], kh[1]);
                    mma16816(s[2 * np + 1], ah, kh[2], kh[3]);
                    mma16816(s[2 * np + 1], ah, kl[2], kl[3]);
                    mma16816(s[2 * np + 1], al, kh[2], kh[3]);
                }
            }

            // fixed-shift softmax + PV, interleaved per key-16 chunk (np)
            const bool diag = (kt >= 2 * qt);
            #pragma unroll
            for (int np = 0; np < 4; np++) {
                uint32_t pah[4], pal[4];
                #pragma unroll
                for (int nn = 0; nn < 2; nn++) {
                    const int n = 2 * np + nn;
                    const int kg = kt * 64 + (n << 3) + ((lane & 3) << 1);
                    float v0 = fmaf(s[n][0], 0.125f, -MSHIFT);
                    float v1 = fmaf(s[n][1], 0.125f, -MSHIFT);
                    float v2 = fmaf(s[n][2], 0.125f, -MSHIFT);
                    float v3 = fmaf(s[n][3], 0.125f, -MSHIFT);
                    if (diag) {
                        if (kg     > qg0) v0 = -1e30f;
                        if (kg + 1 > qg0) v1 = -1e30f;
                        if (kg     > qg1) v2 = -1e30f;
                        if (kg + 1 > qg1) v3 = -1e30f;
                    }
                    const float p0 = __expf(v0), p1 = __expf(v1);
                    const float p2 = __expf(v2), p3 = __expf(v3);
                    l0 += p0 + p1; l1 += p2 + p3;
                    float h0, lo0, h1, lo1, h2, lo2, h3, lo3;
                    splitf(p0, h0, lo0); splitf(p1, h1, lo1);
                    splitf(p2, h2, lo2); splitf(p3, h3, lo3);
                    const int hf = nn << 1;
                    pah[hf]     = pack2(h0, h1);
                    pah[hf + 1] = pack2(h2, h3);
                    pal[hf]     = pack2(lo0, lo1);
                    pal[hf + 1] = pack2(lo2, lo3);
                }
                #pragma unroll
                for (int dg = 0; dg < 4; dg++) {
                    uint32_t vh[4], vl[4];
                    LDSM4(vh, uVh + dg * 2304 + np * 32);
                    LDSM4(vl, uVl + dg * 2304 + np * 32);
                    mma16816(o[2 * dg],     pah, vh[0], vh[1]);
                    mma16816(o[2 * dg],     pah, vl[0], vl[1]);
                    mma16816(o[2 * dg],     pal, vh[0], vh[1]);
                    mma16816(o[2 * dg + 1], pah, vh[2], vh[3]);
                    mma16816(o[2 * dg + 1], pah, vl[2], vl[3]);
                    mma16816(o[2 * dg + 1], pal, vh[2], vh[3]);
                }
            }
        }

        // l row-sum across the 4 lanes of each row, store partials
        l0 += __shfl_xor_sync(0xffffffffu, l0, 1);
        l0 += __shfl_xor_sync(0xffffffffu, l0, 2);
        l1 += __shfl_xor_sync(0xffffffffu, l1, 1);
        l1 += __shfl_xor_sync(0xffffffffu, l1, 2);

        float* P = g_part + (size_t)item * PART_STRIDE;
        const int r0 = (w << 4) + (lane >> 2), r1 = r0 + 8;
        #pragma unroll
        for (int n = 0; n < 8; n++) {
            const int col = (n << 3) + ((lane & 3) << 1);
            *(float2*)&P[r0 * 64 + col] = make_float2(o[n][0], o[n][1]);
            *(float2*)&P[r1 * 64 + col] = make_float2(o[n][2], o[n][3]);
        }
        if ((lane & 3) == 0) {
            P[8192 + r0] = l0;
            P[8192 + r1] = l1;
        }
        __syncthreads();
    }
}

// ---------------------------------------------------------------------------
__global__ __launch_bounds__(256) void combine_kernel(float* __restrict__ out)
{
    const int blk = blockIdx.x;
    const int b = blk & 3, qt = blk >> 2;
    const int C = (qt + 4) >> 2;
    const int base = base_of(qt);
    const int t = threadIdx.x;
    const int row = t >> 1, d0 = (t & 1) << 5;

    float lsum = 0.f;
    for (int c = 0; c < C; c++)
        lsum += g_part[(size_t)((base + c) << 2 | b) * PART_STRIDE + 8192 + row];
    const float inv = 1.0f / lsum;

    const size_t orow = (size_t)(b * SEQ + qt * 128 + row) * HEADD;
    #pragma unroll
    for (int d4 = 0; d4 < 32; d4 += 4) {
        float4 a = make_float4(0.f, 0.f, 0.f, 0.f);
        for (int c = 0; c < C; c++) {
            const float4 v = *(const float4*)&g_part[
                (size_t)((base + c) << 2 | b) * PART_STRIDE + row * 64 + d0 + d4];
            a.x += v.x; a.y += v.y; a.z += v.z; a.w += v.w;
        }
        *(float4*)&out[orow + d0 + d4] =
            make_float4(a.x * inv, a.y * inv, a.z * inv, a.w * inv);
    }
}

// ---------------------------------------------------------------------------
extern "C" void kernel_launch(void* const* d_in, const int* in_sizes, int n_in,
                              void* d_out, int out_size)
{
    const float* x  = (const float*)d_in[0];
    const float* Wq = (const float*)d_in[1];
    const float* bq = (const float*)d_in[2];
    const float* Wk = (const float*)d_in[3];
    const float* bk = (const float*)d_in[4];
    const float* Wv = (const float*)d_in[5];
    const float* bv = (const float*)d_in[6];
    float* out = (float*)d_out;

    qkv_kernel<<<dim3(128, 3), 256>>>(x, Wq, bq, Wk, bk, Wv, bv);

    cudaFuncSetAttribute(attn_kernel,
                         cudaFuncAttributeMaxDynamicSharedMemorySize, ATTN_SMEM);
    attn_kernel<<<296, 256, ATTN_SMEM>>>();

    combine_kernel<<<128, 256>>>(out);
}

// round 12
// speedup vs baseline: 1.2274x; 1.1824x over previous
#include <cuda_runtime.h>
#include <cuda_bf16.h>
#include <cstdint>

#define EMB    1024
#define HEADD  64
#define BATCH  4
#define SEQ    4096
#define NROWS  (BATCH * SEQ)
#define NITEM  576
#define PART_STRIDE 8320           // 128*64 O + 128 l
#define MSHIFT 8.0f

__device__ __align__(16) __nv_bfloat16 g_xh[(size_t)NROWS * EMB], g_xl[(size_t)NROWS * EMB];
__device__ __align__(16) __nv_bfloat16 g_wth[3 * HEADD * EMB], g_wtl[3 * HEADD * EMB];
__device__ __align__(16) __nv_bfloat16 g_qh[NROWS * HEADD], g_ql[NROWS * HEADD];
__device__ __align__(16) __nv_bfloat16 g_kh[NROWS * HEADD], g_kl[NROWS * HEADD];
__device__ __align__(16) __nv_bfloat16 g_vth[NROWS * HEADD], g_vtl[NROWS * HEADD];
__device__ __align__(16) float g_part[(size_t)NITEM * PART_STRIDE];
__device__ int g_ctr;

__device__ __forceinline__ uint32_t pack2(float a, float b) {
    __nv_bfloat162 t = __floats2bfloat162_rn(a, b);
    return *reinterpret_cast<uint32_t*>(&t);
}
__device__ __forceinline__ void splitf(float v, float& h, float& l) {
    h = __bfloat162float(__float2bfloat16(v));
    l = v - h;
}
__device__ __forceinline__ void mma16816(float* d, const uint32_t* a,
                                         uint32_t b0, uint32_t b1) {
    asm volatile(
        "mma.sync.aligned.m16n8k16.row.col.f32.bf16.bf16.f32 "
        "{%0,%1,%2,%3}, {%4,%5,%6,%7}, {%8,%9}, {%0,%1,%2,%3};\n"
        : "+f"(d[0]), "+f"(d[1]), "+f"(d[2]), "+f"(d[3])
        : "r"(a[0]), "r"(a[1]), "r"(a[2]), "r"(a[3]), "r"(b0), "r"(b1));
}
__device__ __forceinline__ uint32_t smem_u32(const void* p) {
    uint32_t a;
    asm("{ .reg .u64 t; cvta.to.shared.u64 t, %1; cvt.u32.u64 %0, t; }" : "=r"(a) : "l"(p));
    return a;
}
#define LDSM4(r, a)                                                          \
    asm volatile("ldmatrix.sync.aligned.m8n8.x4.shared.b16 {%0,%1,%2,%3}, [%4];" \
        : "=r"((r)[0]), "=r"((r)[1]), "=r"((r)[2]), "=r"((r)[3]) : "r"(a))

// ---------------------------------------------------------------------------
// prep: split x into bf16 hi/lo planes; split W into transposed hi/lo planes.
// grid 16384 x 256 thr, one float4 of x per thread. Blocks < 192 also do W.
// ---------------------------------------------------------------------------
__global__ __launch_bounds__(256) void prep_kernel(
    const float* __restrict__ x,
    const float* __restrict__ Wq, const float* __restrict__ Wk,
    const float* __restrict__ Wv)
{
    const size_t idx = (size_t)blockIdx.x * 256 + threadIdx.x;
    if (idx == 0) g_ctr = 0;

    const float4 v = ((const float4*)x)[idx];
    float h0, l0, h1, l1, h2, l2, h3, l3;
    splitf(v.x, h0, l0); splitf(v.y, h1, l1);
    splitf(v.z, h2, l2); splitf(v.w, h3, l3);
    uint2 hh, ll;
    hh.x = pack2(h0, h1); hh.y = pack2(h2, h3);
    ll.x = pack2(l0, l1); ll.y = pack2(l2, l3);
    ((uint2*)g_xh)[idx] = hh;
    ((uint2*)g_xl)[idx] = ll;

    if (blockIdx.x < 192) {
        // W: 3 * 65536 elements; 192*256 threads * 4 each (along n)
        const int e0 = (int)(idx * 4);           // element id within [0, 196608)
        const int sel = e0 >> 16;
        const int r = e0 & 65535;
        const int k = r >> 6, n0 = r & 63;
        const float* W = sel == 0 ? Wq : (sel == 1 ? Wk : Wv);
        const float4 wv = *(const float4*)(W + (size_t)k * HEADD + n0);
        const float wf[4] = {wv.x, wv.y, wv.z, wv.w};
        #pragma unroll
        for (int i = 0; i < 4; i++) {
            float h, l; splitf(wf[i], h, l);
            const size_t o = (size_t)sel * HEADD * EMB + (size_t)(n0 + i) * EMB + k;
            g_wth[o] = __float2bfloat16(h);
            g_wtl[o] = __float2bfloat16(l);
        }
    }
}

// ---------------------------------------------------------------------------
// QKV GEMM on pre-split planes. grid (128, 3), 256 thr (8 warps x 16 rows).
// K-chunk 64. Dyn smem (144 B padded rows):
//   XH 0 (128x144), XL 18432, WH 36864 (64x144), WL 46080. Total 55296 B.
// ---------------------------------------------------------------------------
#define Q_XH 0
#define Q_XL 18432
#define Q_WH 36864
#define Q_WL 46080
#define QKV_SMEM 55296

__global__ __launch_bounds__(256) void qkv_kernel(
    const float* __restrict__ bq, const float* __restrict__ bk,
    const float* __restrict__ bv)
{
    extern __shared__ __align__(16) char smb[];
    const int sel = blockIdx.y;
    const float* bias = sel == 0 ? bq : (sel == 1 ? bk : bv);

    const int t = threadIdx.x, w = t >> 5, lane = t & 31;
    const int row0 = blockIdx.x * 128;
    const uint32_t sb = smem_u32(smb);

    const int tr = lane & 7, tq = lane >> 3;
    const uint32_t uXh = sb + Q_XH
        + (uint32_t)((w * 16 + tr + ((tq & 1) << 3)) * 144 + ((tq >> 1) << 4));
    const uint32_t uXl = uXh + (Q_XL - Q_XH);
    const uint32_t ub = (uint32_t)(((((tq >> 1) << 3) + tr) * 144) + ((tq & 1) << 4));
    const uint32_t uWh = sb + Q_WH + ub;
    const uint32_t uWl = sb + Q_WL + ub;

    float acc[8][4];
    #pragma unroll
    for (int n = 0; n < 8; n++)
        #pragma unroll
        for (int c = 0; c < 4; c++) acc[n][c] = 0.f;

    for (int k0 = 0; k0 < EMB; k0 += 64) {
        __syncthreads();
        // stage X tile: 1024 uint4 per plane
        {
            const uint4* gxh = (const uint4*)g_xh;
            const uint4* gxl = (const uint4*)g_xl;
            #pragma unroll
            for (int i = 0; i < 4; i++) {
                const int idx = t + 256 * i;
                const int r = idx >> 3, c16 = idx & 7;
                const size_t src = (size_t)(row0 + r) * 128 + (k0 >> 3) + c16;
                const uint32_t off = (uint32_t)(r * 144 + c16 * 16);
                *(uint4*)(smb + Q_XH + off) = gxh[src];
                *(uint4*)(smb + Q_XL + off) = gxl[src];
            }
        }
        // stage W tile: 512 uint4 per plane
        {
            const uint4* gwh = (const uint4*)g_wth + (size_t)sel * HEADD * 128;
            const uint4* gwl = (const uint4*)g_wtl + (size_t)sel * HEADD * 128;
            #pragma unroll
            for (int i = 0; i < 2; i++) {
                const int idx = t + 256 * i;
                const int r = idx >> 3, c16 = idx & 7;
                const size_t src = (size_t)r * 128 + (k0 >> 3) + c16;
                const uint32_t off = (uint32_t)(r * 144 + c16 * 16);
                *(uint4*)(smb + Q_WH + off) = gwh[src];
                *(uint4*)(smb + Q_WL + off) = gwl[src];
            }
        }
        __syncthreads();

        #pragma unroll
        for (int ss = 0; ss < 4; ss++) {
            uint32_t ah[4], al[4];
            LDSM4(ah, uXh + ss * 32);
            LDSM4(al, uXl + ss * 32);
            #pragma unroll
            for (int np = 0; np < 4; np++) {
                uint32_t wh[4], wl[4];
                LDSM4(wh, uWh + np * 2304 + ss * 32);
                LDSM4(wl, uWl + np * 2304 + ss * 32);
                mma16816(acc[2 * np],     ah, wh[0], wh[1]);
                mma16816(acc[2 * np],     ah, wl[0], wl[1]);
                mma16816(acc[2 * np],     al, wh[0], wh[1]);
                mma16816(acc[2 * np + 1], ah, wh[2], wh[3]);
                mma16816(acc[2 * np + 1], ah, wl[2], wl[3]);
                mma16816(acc[2 * np + 1], al, wh[2], wh[3]);
            }
        }
    }

    const int r0 = row0 + (w << 4) + (lane >> 2);
    const int r1 = r0 + 8;
    #pragma unroll
    for (int n = 0; n < 8; n++) {
        const int col0 = (n << 3) + ((lane & 3) << 1);
        const float b0 = bias[col0], b1 = bias[col0 + 1];
        const float v00 = acc[n][0] + b0, v01 = acc[n][1] + b1;
        const float v10 = acc[n][2] + b0, v11 = acc[n][3] + b1;
        float h00, l00, h01, l01, h10, l10, h11, l11;
        splitf(v00, h00, l00); splitf(v01, h01, l01);
        splitf(v10, h10, l10); splitf(v11, h11, l11);
        if (sel < 2) {
            __nv_bfloat16* oh = sel ? g_kh : g_qh;
            __nv_bfloat16* ol = sel ? g_kl : g_ql;
            ((uint32_t*)oh)[r0 * 32 + (col0 >> 1)] = pack2(h00, h01);
            ((uint32_t*)oh)[r1 * 32 + (col0 >> 1)] = pack2(h10, h11);
            ((uint32_t*)ol)[r0 * 32 + (col0 >> 1)] = pack2(l00, l01);
            ((uint32_t*)ol)[r1 * 32 + (col0 >> 1)] = pack2(l10, l11);
        } else {
            const int b0i = r0 >> 12, s0 = r0 & 4095;
            const int b1i = r1 >> 12, s1 = r1 & 4095;
            g_vth[((size_t)b0i * 64 + col0) * SEQ + s0]     = __float2bfloat16(h00);
            g_vth[((size_t)b0i * 64 + col0 + 1) * SEQ + s0] = __float2bfloat16(h01);
            g_vth[((size_t)b1i * 64 + col0) * SEQ + s1]     = __float2bfloat16(h10);
            g_vth[((size_t)b1i * 64 + col0 + 1) * SEQ + s1] = __float2bfloat16(h11);
            g_vtl[((size_t)b0i * 64 + col0) * SEQ + s0]     = __float2bfloat16(l00);
            g_vtl[((size_t)b0i * 64 + col0 + 1) * SEQ + s0] = __float2bfloat16(l01);
            g_vtl[((size_t)b1i * 64 + col0) * SEQ + s1]     = __float2bfloat16(l10);
            g_vtl[((size_t)b1i * 64 + col0 + 1) * SEQ + s1] = __float2bfloat16(l11);
        }
    }
}

// ---------------------------------------------------------------------------
__device__ __forceinline__ void decode_item(int j, int& qt, int& c) {
    int acc = 0;
    for (int q = 31; q >= 0; q--) {
        const int n = (q + 4) >> 2;
        if (j < acc + n) { qt = q; c = j - acc; return; }
        acc += n;
    }
    qt = 0; c = 0;
}
__device__ __forceinline__ int base_of(int qt) {
    int acc = 0;
    for (int q = 31; q > qt; q--) acc += (q + 4) >> 2;
    return acc;
}

// ---------------------------------------------------------------------------
// Flash attention (round-11 proven version, unchanged).
// ---------------------------------------------------------------------------
#define A_QH 0
#define A_QL 18432
#define A_KH 36864
#define A_KL 46080
#define A_VH 55296
#define A_VL 64512
#define ATTN_SMEM 73728

__global__ __launch_bounds__(256, 2) void attn_kernel()
{
    extern __shared__ __align__(16) char smb[];
    __shared__ int s_item;

    const int t = threadIdx.x, w = t >> 5, lane = t & 31;
    const uint32_t sb = smem_u32(smb);

    const int tr = lane & 7, tq = lane >> 3;
    const uint32_t uQh = sb + A_QH
        + (uint32_t)((w * 16 + tr + ((tq & 1) << 3)) * 144 + ((tq >> 1) << 4));
    const uint32_t uQl = uQh + (A_QL - A_QH);
    const uint32_t ubase = (uint32_t)(((((tq >> 1) << 3) + tr) * 144) + ((tq & 1) << 4));
    const uint32_t uKh = sb + A_KH + ubase;
    const uint32_t uKl = sb + A_KL + ubase;
    const uint32_t uVh = sb + A_VH + ubase;
    const uint32_t uVl = sb + A_VL + ubase;

    for (;;) {
        if (t == 0) s_item = atomicAdd(&g_ctr, 1);
        __syncthreads();
        const int item = s_item;
        if (item >= NITEM) return;
        const int j = item >> 2, b = item & 3;
        int qt, c; decode_item(j, qt, c);
        const int kt0 = c * 8;
        const int kt1 = min(kt0 + 8, 2 * qt + 2);
        const int qg0 = qt * 128 + (w << 4) + (lane >> 2);
        const int qg1 = qg0 + 8;

        {
            const uint4* gqh = (const uint4*)g_qh + (size_t)(b * SEQ + qt * 128) * 8;
            const uint4* gql = (const uint4*)g_ql + (size_t)(b * SEQ + qt * 128) * 8;
            #pragma unroll
            for (int i = 0; i < 4; i++) {
                const int idx = t + 256 * i;
                const int r = idx >> 3, c16 = idx & 7;
                const uint32_t off = (uint32_t)(r * 144 + c16 * 16);
                *(uint4*)(smb + A_QH + off) = gqh[idx];
                *(uint4*)(smb + A_QL + off) = gql[idx];
            }
        }

        float l0 = 0.f, l1 = 0.f;
        float o[8][4];
        #pragma unroll
        for (int n = 0; n < 8; n++)
            #pragma unroll
            for (int cc = 0; cc < 4; cc++) o[n][cc] = 0.f;

        for (int kt = kt0; kt < kt1; kt++) {
            __syncthreads();
            {
                const uint4* gkh = (const uint4*)g_kh + (size_t)(b * SEQ + kt * 64) * 8;
                const uint4* gkl = (const uint4*)g_kl + (size_t)(b * SEQ + kt * 64) * 8;
                const uint4* gvh = (const uint4*)g_vth;
                const uint4* gvl = (const uint4*)g_vtl;
                #pragma unroll
                for (int i = 0; i < 2; i++) {
                    const int idx = t + 256 * i;
                    const int r = idx >> 3, c16 = idx & 7;
                    const uint32_t off = (uint32_t)(r * 144 + c16 * 16);
                    *(uint4*)(smb + A_KH + off) = gkh[idx];
                    *(uint4*)(smb + A_KL + off) = gkl[idx];
                    const size_t vi = (size_t)(b * 64 + r) * 512 + kt * 8 + c16;
                    *(uint4*)(smb + A_VH + off) = gvh[vi];
                    *(uint4*)(smb + A_VL + off) = gvl[vi];
                }
            }
            __syncthreads();

            float s[8][4];
            #pragma unroll
            for (int n = 0; n < 8; n++)
                #pragma unroll
                for (int cc = 0; cc < 4; cc++) s[n][cc] = 0.f;
            #pragma unroll
            for (int ss = 0; ss < 4; ss++) {
                uint32_t ah[4], al[4];
                LDSM4(ah, uQh + ss * 32);
                LDSM4(al, uQl + ss * 32);
                #pragma unroll
                for (int np = 0; np < 4; np++) {
                    uint32_t kh[4], kl[4];
                    LDSM4(kh, uKh + np * 2304 + ss * 32);
                    LDSM4(kl, uKl + np * 2304 + ss * 32);
                    mma16816(s[2 * np],     ah, kh[0], kh[1]);
                    mma16816(s[2 * np],     ah, kl[0], kl[1]);
                    mma16816(s[2 * np],     al, kh[0], kh[1]);
                    mma16816(s[2 * np + 1], ah, kh[2], kh[3]);
                    mma16816(s[2 * np + 1], ah, kl[2], kl[3]);
                    mma16816(s[2 * np + 1], al, kh[2], kh[3]);
                }
            }

            const bool diag = (kt >= 2 * qt);
            #pragma unroll
            for (int np = 0; np < 4; np++) {
                uint32_t pah[4], pal[4];
                #pragma unroll
                for (int nn = 0; nn < 2; nn++) {
                    const int n = 2 * np + nn;
                    const int kg = kt * 64 + (n << 3) + ((lane & 3) << 1);
                    float v0 = fmaf(s[n][0], 0.125f, -MSHIFT);
                    float v1 = fmaf(s[n][1], 0.125f, -MSHIFT);
                    float v2 = fmaf(s[n][2], 0.125f, -MSHIFT);
                    float v3 = fmaf(s[n][3], 0.125f, -MSHIFT);
                    if (diag) {
                        if (kg     > qg0) v0 = -1e30f;
                        if (kg + 1 > qg0) v1 = -1e30f;
                        if (kg     > qg1) v2 = -1e30f;
                        if (kg + 1 > qg1) v3 = -1e30f;
                    }
                    const float p0 = __expf(v0), p1 = __expf(v1);
                    const float p2 = __expf(v2), p3 = __expf(v3);
                    l0 += p0 + p1; l1 += p2 + p3;
                    float h0, lo0, h1, lo1, h2, lo2, h3, lo3;
                    splitf(p0, h0, lo0); splitf(p1, h1, lo1);
                    splitf(p2, h2, lo2); splitf(p3, h3, lo3);
                    const int hf = nn << 1;
                    pah[hf]     = pack2(h0, h1);
                    pah[hf + 1] = pack2(h2, h3);
                    pal[hf]     = pack2(lo0, lo1);
                    pal[hf + 1] = pack2(lo2, lo3);
                }
                #pragma unroll
                for (int dg = 0; dg < 4; dg++) {
                    uint32_t vh[4], vl[4];
                    LDSM4(vh, uVh + dg * 2304 + np * 32);
                    LDSM4(vl, uVl + dg * 2304 + np * 32);
                    mma16816(o[2 * dg],     pah, vh[0], vh[1]);
                    mma16816(o[2 * dg],     pah, vl[0], vl[1]);
                    mma16816(o[2 * dg],     pal, vh[0], vh[1]);
                    mma16816(o[2 * dg + 1], pah, vh[2], vh[3]);
                    mma16816(o[2 * dg + 1], pah, vl[2], vl[3]);
                    mma16816(o[2 * dg + 1], pal, vh[2], vh[3]);
                }
            }
        }

        l0 += __shfl_xor_sync(0xffffffffu, l0, 1);
        l0 += __shfl_xor_sync(0xffffffffu, l0, 2);
        l1 += __shfl_xor_sync(0xffffffffu, l1, 1);
        l1 += __shfl_xor_sync(0xffffffffu, l1, 2);

        float* P = g_part + (size_t)item * PART_STRIDE;
        const int r0 = (w << 4) + (lane >> 2), r1 = r0 + 8;
        #pragma unroll
        for (int n = 0; n < 8; n++) {
            const int col = (n << 3) + ((lane & 3) << 1);
            *(float2*)&P[r0 * 64 + col] = make_float2(o[n][0], o[n][1]);
            *(float2*)&P[r1 * 64 + col] = make_float2(o[n][2], o[n][3]);
        }
        if ((lane & 3) == 0) {
            P[8192 + r0] = l0;
            P[8192 + r1] = l1;
        }
        __syncthreads();
    }
}

// ---------------------------------------------------------------------------
__global__ __launch_bounds__(256) void combine_kernel(float* __restrict__ out)
{
    const int blk = blockIdx.x;
    const int b = blk & 3, qt = blk >> 2;
    const int C = (qt + 4) >> 2;
    const int base = base_of(qt);
    const int t = threadIdx.x;
    const int row = t >> 1, d0 = (t & 1) << 5;

    float lsum = 0.f;
    for (int c = 0; c < C; c++)
        lsum += g_part[(size_t)((base + c) << 2 | b) * PART_STRIDE + 8192 + row];
    const float inv = 1.0f / lsum;

    const size_t orow = (size_t)(b * SEQ + qt * 128 + row) * HEADD;
    #pragma unroll
    for (int d4 = 0; d4 < 32; d4 += 4) {
        float4 a = make_float4(0.f, 0.f, 0.f, 0.f);
        for (int c = 0; c < C; c++) {
            const float4 v = *(const float4*)&g_part[
                (size_t)((base + c) << 2 | b) * PART_STRIDE + row * 64 + d0 + d4];
            a.x += v.x; a.y += v.y; a.z += v.z; a.w += v.w;
        }
        *(float4*)&out[orow + d0 + d4] =
            make_float4(a.x * inv, a.y * inv, a.z * inv, a.w * inv);
    }
}

// ---------------------------------------------------------------------------
extern "C" void kernel_launch(void* const* d_in, const int* in_sizes, int n_in,
                              void* d_out, int out_size)
{
    const float* x  = (const float*)d_in[0];
    const float* Wq = (const float*)d_in[1];
    const float* bq = (const float*)d_in[2];
    const float* Wk = (const float*)d_in[3];
    const float* bk = (const float*)d_in[4];
    const float* Wv = (const float*)d_in[5];
    const float* bv = (const float*)d_in[6];
    float* out = (float*)d_out;

    prep_kernel<<<NROWS * EMB / 1024, 256>>>(x, Wq, Wk, Wv);

    cudaFuncSetAttribute(qkv_kernel,
                         cudaFuncAttributeMaxDynamicSharedMemorySize, QKV_SMEM);
    qkv_kernel<<<dim3(128, 3), 256, QKV_SMEM>>>(bq, bk, bv);

    cudaFuncSetAttribute(attn_kernel,
                         cudaFuncAttributeMaxDynamicSharedMemorySize, ATTN_SMEM);
    attn_kernel<<<296, 256, ATTN_SMEM>>>();

    combine_kernel<<<128, 256>>>(out);
}